// round 9
// baseline (speedup 1.0000x reference)
#include <cuda_runtime.h>
#include <cuda_bf16.h>
#include <cstdint>

// ---------------------------------------------------------------------------
// Problem constants
// ---------------------------------------------------------------------------
#define B_  8192
#define D_  1024
#define O_  1024
#define E_  8

// GEMM tiling
#define BM 128
#define BN 64
#define KSTG 64                     // k per stage
#define STAGES 6
#define NST (E_ * D_ / KSTG)        // 128 stages (16 per expert)
#define STAGEB 24576                // A0 8K | A1 8K | B0 4K | B1 4K

// SMEM layout
#define SM_GS 0                     // gates  [8][128] f32 = 4 KB
#define SM_SW 4096                  // sw     [8][64]  f32 = 2 KB
#define SM_BE 6144                  // bias   [8][64]  f32 = 2 KB
#define SM_ST 8192
#define SMEM_TOTAL (SM_ST + STAGES * STAGEB)   // 155648

// ---------------------------------------------------------------------------
// Scratch (device globals — no allocation)
// ---------------------------------------------------------------------------
__device__ float g_gates[B_ * E_];
__device__ float g_sx[B_];                         // per-row x scale
__device__ float g_swf[E_ * O_];                   // per-(e,col) W scale
__device__ __align__(16) signed char g_x0[B_ * D_];
__device__ __align__(16) signed char g_x1[B_ * D_];
__device__ __align__(16) signed char g_w0[E_ * O_ * D_];   // [e][o][k]
__device__ __align__(16) signed char g_w1[E_ * O_ * D_];

// ---------------------------------------------------------------------------
// Helpers
// ---------------------------------------------------------------------------
__device__ __forceinline__ uint32_t smem_u32(const void* p) {
    uint32_t a;
    asm("{ .reg .u64 t; cvta.to.shared.u64 t, %1; cvt.u32.u64 %0, t; }" : "=r"(a) : "l"(p));
    return a;
}
#define SWZ64(x) ((x) ^ (((x) >> 3) & 0x30))

__device__ __forceinline__ void cpa16(uint32_t dst, const void* src) {
    asm volatile("cp.async.cg.shared.global [%0], [%1], 16;" :: "r"(dst), "l"(src) : "memory");
}

#define LDSM4(r, addr) \
    asm volatile("ldmatrix.sync.aligned.m8n8.x4.shared.b16 {%0,%1,%2,%3}, [%4];" \
        : "=r"((r)[0]), "=r"((r)[1]), "=r"((r)[2]), "=r"((r)[3]) : "r"(addr))

#define IMMA(c, a, b) \
    asm volatile("mma.sync.aligned.m16n8k32.row.col.s32.s8.s8.s32 " \
        "{%0,%1,%2,%3}, {%4,%5,%6,%7}, {%8,%9}, {%0,%1,%2,%3};" \
        : "+r"((c)[0]), "+r"((c)[1]), "+r"((c)[2]), "+r"((c)[3]) \
        : "r"((a)[0]), "r"((a)[1]), "r"((a)[2]), "r"((a)[3]), \
          "r"((b)[0]), "r"((b)[1]))

// ---------------------------------------------------------------------------
// Kernel 1: gating (validated)
// ---------------------------------------------------------------------------
__global__ void gates_kernel(const float* __restrict__ x,
                             const float* __restrict__ Wg,
                             const float* __restrict__ bg) {
    int warp = (blockIdx.x * blockDim.x + threadIdx.x) >> 5;
    int lane = threadIdx.x & 31;
    if (warp >= B_) return;
    const float* xr = x + (size_t)warp * D_;
    float acc[E_];
#pragma unroll
    for (int e = 0; e < E_; e++) acc[e] = 0.f;
    for (int d = lane; d < D_; d += 32) {
        float xv = xr[d];
        const float4* w4 = reinterpret_cast<const float4*>(Wg + d * E_);
        float4 w0 = w4[0], w1 = w4[1];
        acc[0] += xv * w0.x; acc[1] += xv * w0.y;
        acc[2] += xv * w0.z; acc[3] += xv * w0.w;
        acc[4] += xv * w1.x; acc[5] += xv * w1.y;
        acc[6] += xv * w1.z; acc[7] += xv * w1.w;
    }
#pragma unroll
    for (int e = 0; e < E_; e++)
#pragma unroll
        for (int off = 16; off; off >>= 1)
            acc[e] += __shfl_xor_sync(0xffffffffu, acc[e], off);
    if (lane == 0) {
        float m = -1e30f;
#pragma unroll
        for (int e = 0; e < E_; e++) { acc[e] += bg[e]; m = fmaxf(m, acc[e]); }
        float s = 0.f;
#pragma unroll
        for (int e = 0; e < E_; e++) { acc[e] = expf(acc[e] - m); s += acc[e]; }
        float inv = 1.f / s;
#pragma unroll
        for (int e = 0; e < E_; e++) g_gates[warp * E_ + e] = acc[e] * inv;
    }
}

// ---------------------------------------------------------------------------
// Kernel 2: quantize x rows to two-level int8 (per-row scale)
// ---------------------------------------------------------------------------
__global__ void quant_x_kernel(const float* __restrict__ x) {
    int row = blockIdx.x * 8 + (threadIdx.x >> 5);
    int lane = threadIdx.x & 31;
    const float* xr = x + (size_t)row * D_;

    float m = 0.f;
    float4 v[8];
#pragma unroll
    for (int i = 0; i < 8; i++) {
        v[i] = reinterpret_cast<const float4*>(xr)[lane + i * 32];
        m = fmaxf(m, fmaxf(fmaxf(fabsf(v[i].x), fabsf(v[i].y)),
                           fmaxf(fabsf(v[i].z), fabsf(v[i].w))));
    }
#pragma unroll
    for (int off = 16; off; off >>= 1)
        m = fmaxf(m, __shfl_xor_sync(0xffffffffu, m, off));
    float inv = (m > 0.f) ? 127.f / m : 0.f;
    if (lane == 0) g_sx[row] = m / 127.f;

#pragma unroll
    for (int i = 0; i < 8; i++) {
        float q[4] = {v[i].x * inv, v[i].y * inv, v[i].z * inv, v[i].w * inv};
        char c0[4], c1[4];
#pragma unroll
        for (int c = 0; c < 4; c++) {
            int i0 = __float2int_rn(q[c]);
            int i1 = __float2int_rn((q[c] - (float)i0) * 128.f);
            c0[c] = (char)i0; c1[c] = (char)i1;
        }
        int idx = row * D_ + lane * 4 + i * 128;
        *reinterpret_cast<uint32_t*>(&g_x0[idx]) = *reinterpret_cast<uint32_t*>(c0);
        *reinterpret_cast<uint32_t*>(&g_x1[idx]) = *reinterpret_cast<uint32_t*>(c1);
    }
}

// ---------------------------------------------------------------------------
// Kernel 3: per-(expert,col) W abs-max
// ---------------------------------------------------------------------------
__global__ void colmax_kernel(const float* __restrict__ We) {
    int o = blockIdx.x * 256 + threadIdx.x;
    int e = blockIdx.y;
    const float* base = We + ((size_t)e << 20) + o;
    float m = 0.f;
    for (int k = 0; k < D_; k++) m = fmaxf(m, fabsf(base[(size_t)k * O_]));
    g_swf[e * O_ + o] = m / 127.f;
}

// ---------------------------------------------------------------------------
// Kernel 4: transpose + quantize We[e][k][o] -> w0/w1 [e][o][k]
// ---------------------------------------------------------------------------
__global__ void quantw_kernel(const float* __restrict__ We) {
    __shared__ float t[32][33];
    int e = blockIdx.z;
    int k0 = blockIdx.y * 32, n0 = blockIdx.x * 32;
    int tx = threadIdx.x, ty = threadIdx.y;
    const float* base = We + ((size_t)e << 20);
#pragma unroll
    for (int j = 0; j < 4; j++)
        t[ty + j * 8][tx] = base[(size_t)(k0 + ty + j * 8) * O_ + n0 + tx];
    __syncthreads();
#pragma unroll
    for (int j = 0; j < 4; j++) {
        int o = n0 + ty + j * 8;
        float s = g_swf[e * O_ + o];
        float inv = (s > 0.f) ? 1.f / s : 0.f;
        float q = t[tx][ty + j * 8] * inv;
        int i0 = __float2int_rn(q);
        int i1 = __float2int_rn((q - (float)i0) * 128.f);
        size_t idx = ((size_t)e << 20) + (size_t)o * D_ + k0 + tx;
        g_w0[idx] = (char)i0;
        g_w1[idx] = (char)i1;
    }
}

// ---------------------------------------------------------------------------
// Kernel 5: main MoE GEMM on int8 tensor cores
//   out = sum_e g_e * ( sx_row * sw_col * (c00 + (c01+c10)/128) + be )
// ---------------------------------------------------------------------------
__global__ __launch_bounds__(256, 1)
void moe_imma_kernel(const float* __restrict__ be, float* __restrict__ out) {
    extern __shared__ char smem[];
    const uint32_t sb = smem_u32(smem);
    const int tid = threadIdx.x;
    const int lane = tid & 31;
    const int wid = tid >> 5;
    const int warp_m = wid >> 2;        // 0..1  (64-row slabs)
    const int warp_n = wid & 3;         // 0..3  (16-col slabs)
    const int m0 = blockIdx.y * BM;
    const int n0 = blockIdx.x * BN;

    float* gs   = reinterpret_cast<float*>(smem + SM_GS);   // [8][128]
    float* sw_s = reinterpret_cast<float*>(smem + SM_SW);   // [8][64]
    float* be_s = reinterpret_cast<float*>(smem + SM_BE);   // [8][64]
    for (int i = tid; i < E_ * BM; i += 256)
        gs[i] = g_gates[(size_t)(m0 + (i & 127)) * E_ + (i >> 7)];
    for (int i = tid; i < E_ * BN; i += 256) {
        sw_s[i] = g_swf[(i >> 6) * O_ + n0 + (i & 63)];
        be_s[i] = be[(i >> 6) * O_ + n0 + (i & 63)];
    }

    // stage loader: 6 x 16B cp.async per thread
    auto issue = [&](int s) {
        const int e = s >> 4, kc = s & 15, koff = kc * KSTG;
        const uint32_t stg = sb + SM_ST + (s % STAGES) * STAGEB;
#pragma unroll
        for (int i = 0; i < 6; i++) {
            int c = tid + i * 256;
            if (c < 1024) {                 // A: x0 / x1, 128 rows x 64 k
                int comp = c >> 9, idx = c & 511;
                int r = idx >> 2, k16 = idx & 3;
                uint32_t dst = stg + comp * 8192 + SWZ64(r * 64 + k16 * 16);
                const signed char* src = (comp ? g_x1 : g_x0)
                    + (size_t)(m0 + r) * D_ + koff + k16 * 16;
                cpa16(dst, src);
            } else {                        // B: w0 / w1, 64 rows x 64 k
                int cb = c - 1024;
                int comp = cb >> 8, idx = cb & 255;
                int r = idx >> 2, k16 = idx & 3;
                uint32_t dst = stg + 16384 + comp * 4096 + SWZ64(r * 64 + k16 * 16);
                const signed char* src = (comp ? g_w1 : g_w0)
                    + ((size_t)e * O_ + n0 + r) * D_ + koff + k16 * 16;
                cpa16(dst, src);
            }
        }
        asm volatile("cp.async.commit_group;" ::: "memory");
    };

#pragma unroll
    for (int ps = 0; ps < 5; ps++) issue(ps);
    __syncthreads();

    // per-thread row scales (8 rows owned by this thread)
    float sxl[4], sxh[4];
#pragma unroll
    for (int mf = 0; mf < 4; mf++) {
        int r = m0 + warp_m * 64 + mf * 16 + (lane >> 2);
        sxl[mf] = g_sx[r];
        sxh[mf] = g_sx[r + 8];
    }

    // accumulators
    float acc_t[4][2][4];
    int c00[4][2][4], c01[4][2][4];
#pragma unroll
    for (int mf = 0; mf < 4; mf++)
#pragma unroll
        for (int nf = 0; nf < 2; nf++)
#pragma unroll
            for (int j = 0; j < 4; j++) {
                acc_t[mf][nf][j] = 0.f; c00[mf][nf][j] = 0; c01[mf][nf][j] = 0;
            }

    // bias init: acc_t = sum_e g[e][row] * be[e][col]
#pragma unroll
    for (int e = 0; e < E_; e++) {
#pragma unroll
        for (int mf = 0; mf < 4; mf++) {
            int rl = warp_m * 64 + mf * 16 + (lane >> 2);
            float gl = gs[e * BM + rl], gh = gs[e * BM + rl + 8];
#pragma unroll
            for (int nf = 0; nf < 2; nf++) {
                int cl = warp_n * 16 + nf * 8 + (lane & 3) * 2;
                float b0 = be_s[e * BN + cl], b1 = be_s[e * BN + cl + 1];
                acc_t[mf][nf][0] += gl * b0; acc_t[mf][nf][1] += gl * b1;
                acc_t[mf][nf][2] += gh * b0; acc_t[mf][nf][3] += gh * b1;
            }
        }
    }

    // ldmatrix lane addressing
    const int a_row = lane & 15, a_kb = lane >> 4;
    const int b_row = (lane & 7) + ((lane >> 4) << 3), b_kb = (lane >> 3) & 1;

    for (int s = 0; s < NST; s++) {
        asm volatile("cp.async.wait_group 4;" ::: "memory");
        __syncthreads();
        if (s + 5 < NST) issue(s + 5);
        else asm volatile("cp.async.commit_group;" ::: "memory");

        const uint32_t stg = sb + SM_ST + (s % STAGES) * STAGEB;

#pragma unroll
        for (int kk = 0; kk < 2; kk++) {      // two k32 steps
            uint32_t a0[4][4], a1[4][4], b0[2][2], b1[2][2];
#pragma unroll
            for (int mf = 0; mf < 4; mf++) {
                int row = warp_m * 64 + mf * 16 + a_row;
                uint32_t off = SWZ64(row * 64 + kk * 32 + a_kb * 16);
                LDSM4(a0[mf], stg + off);
                LDSM4(a1[mf], stg + 8192 + off);
            }
            {
                int n = warp_n * 16 + b_row;
                uint32_t off = SWZ64(n * 64 + kk * 32 + b_kb * 16);
                uint32_t t[4];
                LDSM4(t, stg + 16384 + off);
                b0[0][0] = t[0]; b0[0][1] = t[1]; b0[1][0] = t[2]; b0[1][1] = t[3];
                LDSM4(t, stg + 20480 + off);
                b1[0][0] = t[0]; b1[0][1] = t[1]; b1[1][0] = t[2]; b1[1][1] = t[3];
            }
#pragma unroll
            for (int mf = 0; mf < 4; mf++)
#pragma unroll
                for (int nf = 0; nf < 2; nf++) {
                    IMMA(c00[mf][nf], a0[mf], b0[nf]);
                    IMMA(c01[mf][nf], a0[mf], b1[nf]);
                    IMMA(c01[mf][nf], a1[mf], b0[nf]);
                }
        }

        if ((s & 15) == 15) {                 // expert boundary: combine
            const int e = s >> 4;
#pragma unroll
            for (int mf = 0; mf < 4; mf++) {
                int rl = warp_m * 64 + mf * 16 + (lane >> 2);
                float fl = gs[e * BM + rl] * sxl[mf];
                float fh = gs[e * BM + rl + 8] * sxh[mf];
#pragma unroll
                for (int nf = 0; nf < 2; nf++) {
                    int cl = warp_n * 16 + nf * 8 + (lane & 3) * 2;
                    float s0 = sw_s[e * BN + cl], s1 = sw_s[e * BN + cl + 1];
                    float v0 = (float)c00[mf][nf][0] + 0.0078125f * (float)c01[mf][nf][0];
                    float v1 = (float)c00[mf][nf][1] + 0.0078125f * (float)c01[mf][nf][1];
                    float v2 = (float)c00[mf][nf][2] + 0.0078125f * (float)c01[mf][nf][2];
                    float v3 = (float)c00[mf][nf][3] + 0.0078125f * (float)c01[mf][nf][3];
                    acc_t[mf][nf][0] += fl * s0 * v0;
                    acc_t[mf][nf][1] += fl * s1 * v1;
                    acc_t[mf][nf][2] += fh * s0 * v2;
                    acc_t[mf][nf][3] += fh * s1 * v3;
                    c00[mf][nf][0] = 0; c00[mf][nf][1] = 0;
                    c00[mf][nf][2] = 0; c00[mf][nf][3] = 0;
                    c01[mf][nf][0] = 0; c01[mf][nf][1] = 0;
                    c01[mf][nf][2] = 0; c01[mf][nf][3] = 0;
                }
            }
        }
    }

    // store 64x16 warp tile
#pragma unroll
    for (int mf = 0; mf < 4; mf++) {
        size_t rl = (size_t)(m0 + warp_m * 64 + mf * 16 + (lane >> 2));
#pragma unroll
        for (int nf = 0; nf < 2; nf++) {
            int n = n0 + warp_n * 16 + nf * 8 + (lane & 3) * 2;
            *reinterpret_cast<float2*>(out + rl * O_ + n) =
                make_float2(acc_t[mf][nf][0], acc_t[mf][nf][1]);
            *reinterpret_cast<float2*>(out + (rl + 8) * O_ + n) =
                make_float2(acc_t[mf][nf][2], acc_t[mf][nf][3]);
        }
    }
}

// ---------------------------------------------------------------------------
extern "C" void kernel_launch(void* const* d_in, const int* in_sizes, int n_in,
                              void* d_out, int out_size) {
    const float* x  = (const float*)d_in[0];   // [8192, 1024]
    const float* Wg = (const float*)d_in[1];   // [1024, 8]
    const float* bg = (const float*)d_in[2];   // [8]
    const float* We = (const float*)d_in[3];   // [8, 1024, 1024]
    const float* be = (const float*)d_in[4];   // [8, 1024]
    float* out = (float*)d_out;                // [8192, 1024]

    cudaFuncSetAttribute(moe_imma_kernel,
                         cudaFuncAttributeMaxDynamicSharedMemorySize, SMEM_TOTAL);

    gates_kernel<<<B_ / 8, 256>>>(x, Wg, bg);
    quant_x_kernel<<<B_ / 8, 256>>>(x);
    colmax_kernel<<<dim3(O_ / 256, E_), 256>>>(We);
    quantw_kernel<<<dim3(O_ / 32, D_ / 32, E_), dim3(32, 8)>>>(We);

    dim3 grid(O_ / BN, B_ / BM);               // (16, 64) = 1024 CTAs
    moe_imma_kernel<<<grid, 256, SMEM_TOTAL>>>(be, out);
}

// round 10
// speedup vs baseline: 4.0788x; 4.0788x over previous
#include <cuda_runtime.h>
#include <cuda_fp16.h>
#include <cstdint>

// ---------------------------------------------------------------------------
// Problem constants
// ---------------------------------------------------------------------------
#define B_  8192
#define D_  1024
#define O_  1024
#define E_  8

// GEMM tiling
#define BM 128
#define BN 128
#define KSTG 128                    // k per stage
#define NST (E_ * D_ / KSTG)        // 64 stages (8 per expert)
#define SUBT 16384                  // one 128x64 fp16 sub-tile
#define STAGEB (6 * SUBT)           // Ah0 Ah1 Al0 Al1 B0 B1 = 96 KB

// SMEM layout
#define SM_GS 0                     // gates [8][128] f32 = 4 KB
#define SM_BE 4096                  // bias  [8][128] f32 = 4 KB
#define SM_ST 8192
#define SMEM_TOTAL (SM_ST + 2 * STAGEB)   // 204800

// ---------------------------------------------------------------------------
// Scratch (device globals — no allocation)
// ---------------------------------------------------------------------------
__device__ float g_gates[B_ * E_];
__device__ __align__(16) __half g_xh[B_ * D_];
__device__ __align__(16) __half g_xl[B_ * D_];
__device__ __align__(16) __half g_wt[E_ * O_ * D_];   // [e][n][k] K-major fp16

// ---------------------------------------------------------------------------
// Helpers
// ---------------------------------------------------------------------------
__device__ __forceinline__ uint32_t smem_u32(const void* p) {
    uint32_t a;
    asm("{ .reg .u64 t; cvta.to.shared.u64 t, %1; cvt.u32.u64 %0, t; }" : "=r"(a) : "l"(p));
    return a;
}
#define SWZ(x) ((x) ^ (((x) >> 3) & 0x70))

__device__ __forceinline__ void cpa16(uint32_t dst, const void* src) {
    asm volatile("cp.async.cg.shared.global [%0], [%1], 16;" :: "r"(dst), "l"(src) : "memory");
}

#define LDSM4(r, addr) \
    asm volatile("ldmatrix.sync.aligned.m8n8.x4.shared.b16 {%0,%1,%2,%3}, [%4];" \
        : "=r"((r)[0]), "=r"((r)[1]), "=r"((r)[2]), "=r"((r)[3]) : "r"(addr))

#define MMA16816(c, a, b) \
    asm volatile("mma.sync.aligned.m16n8k16.row.col.f32.f16.f16.f32 " \
        "{%0,%1,%2,%3}, {%4,%5,%6,%7}, {%8,%9}, {%0,%1,%2,%3};" \
        : "+f"((c)[0]), "+f"((c)[1]), "+f"((c)[2]), "+f"((c)[3]) \
        : "r"((a)[0]), "r"((a)[1]), "r"((a)[2]), "r"((a)[3]), \
          "r"((b)[0]), "r"((b)[1]))

// ---------------------------------------------------------------------------
// Kernel 1: gating (validated)
// ---------------------------------------------------------------------------
__global__ void gates_kernel(const float* __restrict__ x,
                             const float* __restrict__ Wg,
                             const float* __restrict__ bg) {
    int warp = (blockIdx.x * blockDim.x + threadIdx.x) >> 5;
    int lane = threadIdx.x & 31;
    if (warp >= B_) return;
    const float* xr = x + (size_t)warp * D_;
    float acc[E_];
#pragma unroll
    for (int e = 0; e < E_; e++) acc[e] = 0.f;
    for (int d = lane; d < D_; d += 32) {
        float xv = xr[d];
        const float4* w4 = reinterpret_cast<const float4*>(Wg + d * E_);
        float4 w0 = w4[0], w1 = w4[1];
        acc[0] += xv * w0.x; acc[1] += xv * w0.y;
        acc[2] += xv * w0.z; acc[3] += xv * w0.w;
        acc[4] += xv * w1.x; acc[5] += xv * w1.y;
        acc[6] += xv * w1.z; acc[7] += xv * w1.w;
    }
#pragma unroll
    for (int e = 0; e < E_; e++)
#pragma unroll
        for (int off = 16; off; off >>= 1)
            acc[e] += __shfl_xor_sync(0xffffffffu, acc[e], off);
    if (lane == 0) {
        float m = -1e30f;
#pragma unroll
        for (int e = 0; e < E_; e++) { acc[e] += bg[e]; m = fmaxf(m, acc[e]); }
        float s = 0.f;
#pragma unroll
        for (int e = 0; e < E_; e++) { acc[e] = expf(acc[e] - m); s += acc[e]; }
        float inv = 1.f / s;
#pragma unroll
        for (int e = 0; e < E_; e++) g_gates[warp * E_ + e] = acc[e] * inv;
    }
}

// ---------------------------------------------------------------------------
// Kernel 2: split x -> fp16 hi/lo
// ---------------------------------------------------------------------------
__global__ void split_x_kernel(const float* __restrict__ x) {
    int i = blockIdx.x * blockDim.x + threadIdx.x;   // over float4s
    if (i >= (B_ * D_) / 4) return;
    float4 v = reinterpret_cast<const float4*>(x)[i];
    float vv[4] = {v.x, v.y, v.z, v.w};
    __half h[4], l[4];
#pragma unroll
    for (int c = 0; c < 4; c++) {
        h[c] = __float2half_rn(vv[c]);
        l[c] = __float2half_rn(vv[c] - __half2float(h[c]));
    }
    *reinterpret_cast<uint64_t*>(&g_xh[(size_t)i * 4]) = *reinterpret_cast<uint64_t*>(h);
    *reinterpret_cast<uint64_t*>(&g_xl[(size_t)i * 4]) = *reinterpret_cast<uint64_t*>(l);
}

// ---------------------------------------------------------------------------
// Kernel 3: transpose We[e][k][n] -> fp16 WeT[e][n][k]
// ---------------------------------------------------------------------------
__global__ void wt_kernel(const float* __restrict__ We) {
    __shared__ float t[32][33];
    int e = blockIdx.z;
    int k0 = blockIdx.y * 32, n0 = blockIdx.x * 32;
    int tx = threadIdx.x, ty = threadIdx.y;
    const float* base = We + ((size_t)e << 20);
#pragma unroll
    for (int j = 0; j < 4; j++)
        t[ty + j * 8][tx] = base[(size_t)(k0 + ty + j * 8) * O_ + n0 + tx];
    __syncthreads();
    size_t ob = ((size_t)e << 20);
#pragma unroll
    for (int j = 0; j < 4; j++)
        g_wt[ob + (size_t)(n0 + ty + j * 8) * D_ + k0 + tx] =
            __float2half_rn(t[tx][ty + j * 8]);
}

// ---------------------------------------------------------------------------
// Kernel 4: MoE GEMM (fp16 2-product split, tensor cores)
// ---------------------------------------------------------------------------
__global__ __launch_bounds__(256, 1)
void moe_mma_kernel(const float* __restrict__ be, float* __restrict__ out) {
    extern __shared__ char smem[];
    const uint32_t sb = smem_u32(smem);
    const int tid = threadIdx.x;
    const int lane = tid & 31;
    const int wid = tid >> 5;
    const int warp_m = wid >> 2;        // 0..1  (64-row slabs)
    const int warp_n = wid & 3;         // 0..3  (32-col slabs)
    const int m0 = blockIdx.y * BM;
    const int n0 = blockIdx.x * BN;

    float* gs  = reinterpret_cast<float*>(smem + SM_GS);   // [8][128]
    float* bes = reinterpret_cast<float*>(smem + SM_BE);   // [8][128]
    for (int i = tid; i < E_ * BM; i += 256)
        gs[i] = g_gates[(size_t)(m0 + (i & 127)) * E_ + (i >> 7)];
    for (int i = tid; i < E_ * BN; i += 256)
        bes[i] = be[(i >> 7) * O_ + n0 + (i & 127)];

    float acc_t[4][4][4], acc_e[4][4][4];
#pragma unroll
    for (int a = 0; a < 4; a++)
#pragma unroll
        for (int b = 0; b < 4; b++)
#pragma unroll
            for (int c = 0; c < 4; c++) { acc_t[a][b][c] = 0.f; acc_e[a][b][c] = 0.f; }

    // stage loader: 24 x 16B cp.async per thread (6 sub-tiles of 128x64 fp16)
    // tiles: 0,1 = Ah ksub 0/1 ; 2,3 = Al ksub 0/1 ; 4,5 = B ksub 0/1
    auto issue = [&](int s) {
        const int e = s >> 3, kc = s & 7, koff = kc * KSTG;
        const uint32_t stg = sb + SM_ST + (s & 1) * STAGEB;
#pragma unroll
        for (int i = 0; i < 24; i++) {
            int c = tid + i * 256;
            int tile = c >> 10;
            int loc = c & 1023;
            int r = loc >> 3;            // row 0..127
            int k16 = loc & 7;           // 16B chunk within 128B row
            uint32_t dst = stg + tile * SUBT + SWZ(r * 128 + k16 * 16);
            const __half* src;
            if (tile < 4) {
                const __half* bp = (tile < 2) ? g_xh : g_xl;
                src = bp + (size_t)(m0 + r) * D_ + koff + (tile & 1) * 64 + k16 * 8;
            } else {
                src = g_wt + ((size_t)e * O_ + n0 + r) * D_ + koff + (tile - 4) * 64 + k16 * 8;
            }
            cpa16(dst, src);
        }
        asm volatile("cp.async.commit_group;" ::: "memory");
    };

    issue(0);

    // ldmatrix lane address components
    const int a_row = lane & 15;
    const int a_kb  = lane >> 4;
    const int b_row = (lane & 7) + ((lane >> 4) << 3);
    const int b_kb  = (lane >> 3) & 1;

    for (int s = 0; s < NST; s++) {
        asm volatile("cp.async.wait_group 0;" ::: "memory");
        __syncthreads();                 // stage s visible; buffer (s+1)&1 free
        if (s + 1 < NST) issue(s + 1);   // overlaps with compute below

        const uint32_t stg = sb + SM_ST + (s & 1) * STAGEB;

#pragma unroll
        for (int kk = 0; kk < 8; kk++) {      // 8 k16 steps (2 sub-tiles)
            const uint32_t sub = (uint32_t)(kk >> 2) * SUBT;
            const int kloc = kk & 3;
            uint32_t ah[4][4], al[4][4], bf[4][2];
#pragma unroll
            for (int mf = 0; mf < 4; mf++) {
                int row = warp_m * 64 + mf * 16 + a_row;
                uint32_t off = SWZ(row * 128 + kloc * 32 + a_kb * 16);
                LDSM4(ah[mf], stg + sub + off);
                LDSM4(al[mf], stg + 2 * SUBT + sub + off);
            }
#pragma unroll
            for (int nf2 = 0; nf2 < 2; nf2++) {
                int row = warp_n * 32 + nf2 * 16 + b_row;
                uint32_t off = SWZ(row * 128 + kloc * 32 + b_kb * 16);
                uint32_t t[4];
                LDSM4(t, stg + 4 * SUBT + sub + off);
                bf[nf2 * 2][0] = t[0]; bf[nf2 * 2][1] = t[1];
                bf[nf2 * 2 + 1][0] = t[2]; bf[nf2 * 2 + 1][1] = t[3];
            }
#pragma unroll
            for (int mf = 0; mf < 4; mf++)
#pragma unroll
                for (int nf = 0; nf < 4; nf++) {
                    MMA16816(acc_e[mf][nf], ah[mf], bf[nf]);
                    MMA16816(acc_e[mf][nf], al[mf], bf[nf]);
                }
        }

        if ((s & 7) == 7) {                   // expert boundary: combine
            const int e = s >> 3;
#pragma unroll
            for (int mf = 0; mf < 4; mf++) {
                int rl = warp_m * 64 + mf * 16 + (lane >> 2);
                float ga = gs[e * BM + rl];
                float gb = gs[e * BM + rl + 8];
#pragma unroll
                for (int nf = 0; nf < 4; nf++) {
                    int n = warp_n * 32 + nf * 8 + (lane & 3) * 2;
                    float be0 = bes[e * BN + n], be1 = bes[e * BN + n + 1];
                    acc_t[mf][nf][0] += ga * (acc_e[mf][nf][0] + be0);
                    acc_t[mf][nf][1] += ga * (acc_e[mf][nf][1] + be1);
                    acc_t[mf][nf][2] += gb * (acc_e[mf][nf][2] + be0);
                    acc_t[mf][nf][3] += gb * (acc_e[mf][nf][3] + be1);
                    acc_e[mf][nf][0] = 0.f; acc_e[mf][nf][1] = 0.f;
                    acc_e[mf][nf][2] = 0.f; acc_e[mf][nf][3] = 0.f;
                }
            }
        }
    }

    // store 64x32 warp tile
#pragma unroll
    for (int mf = 0; mf < 4; mf++) {
        size_t r0 = (size_t)(m0 + warp_m * 64 + mf * 16 + (lane >> 2));
#pragma unroll
        for (int nf = 0; nf < 4; nf++) {
            int n = n0 + warp_n * 32 + nf * 8 + (lane & 3) * 2;
            *reinterpret_cast<float2*>(out + r0 * O_ + n) =
                make_float2(acc_t[mf][nf][0], acc_t[mf][nf][1]);
            *reinterpret_cast<float2*>(out + (r0 + 8) * O_ + n) =
                make_float2(acc_t[mf][nf][2], acc_t[mf][nf][3]);
        }
    }
}

// ---------------------------------------------------------------------------
extern "C" void kernel_launch(void* const* d_in, const int* in_sizes, int n_in,
                              void* d_out, int out_size) {
    const float* x  = (const float*)d_in[0];   // [8192, 1024]
    const float* Wg = (const float*)d_in[1];   // [1024, 8]
    const float* bg = (const float*)d_in[2];   // [8]
    const float* We = (const float*)d_in[3];   // [8, 1024, 1024]
    const float* be = (const float*)d_in[4];   // [8, 1024]
    float* out = (float*)d_out;                // [8192, 1024]

    cudaFuncSetAttribute(moe_mma_kernel,
                         cudaFuncAttributeMaxDynamicSharedMemorySize, SMEM_TOTAL);

    gates_kernel<<<B_ / 8, 256>>>(x, Wg, bg);
    split_x_kernel<<<(B_ * D_ / 4 + 255) / 256, 256>>>(x);
    wt_kernel<<<dim3(O_ / 32, D_ / 32, E_), dim3(32, 8)>>>(We);

    dim3 grid(O_ / BN, B_ / BM);               // (8, 64) = 512 CTAs
    moe_mma_kernel<<<grid, 256, SMEM_TOTAL>>>(be, out);
}

// round 11
// speedup vs baseline: 6.4827x; 1.5894x over previous
#include <cuda_runtime.h>
#include <cuda_fp16.h>
#include <cstdint>

// ---------------------------------------------------------------------------
// Problem constants
// ---------------------------------------------------------------------------
#define B_  8192
#define D_  1024
#define O_  1024
#define E_  8

// GEMM tiling: CTA 256x128, 8 warps of 64x64, K=64 per stage
#define BM 256
#define BN 128
#define KSTG 64
#define NST (E_ * D_ / KSTG)        // 128 stages (16 per expert)
#define A_BYTES (BM * 128)          // 32 KB (256 rows x 64 fp16)
#define B_BYTES (BN * 128)          // 16 KB
#define STAGEB (A_BYTES + B_BYTES)  // 48 KB
#define NSTAGE 4

// SMEM layout
#define SM_GS 0                     // gates [8][256] f32 = 8 KB
#define SM_BE 8192                  // bias  [8][128] f32 = 4 KB
#define SM_ST 12288
#define SMEM_TOTAL (SM_ST + NSTAGE * STAGEB)   // 208896

// ---------------------------------------------------------------------------
// Scratch (device globals — no allocation)
// ---------------------------------------------------------------------------
__device__ float g_gates[B_ * E_];
__device__ __align__(16) __half g_gx[(size_t)E_ * B_ * D_];  // gate-scaled x, [e][b][d]
__device__ __align__(16) __half g_wt[E_ * O_ * D_];          // [e][n][k] K-major

// ---------------------------------------------------------------------------
// Helpers
// ---------------------------------------------------------------------------
__device__ __forceinline__ uint32_t smem_u32(const void* p) {
    uint32_t a;
    asm("{ .reg .u64 t; cvta.to.shared.u64 t, %1; cvt.u32.u64 %0, t; }" : "=r"(a) : "l"(p));
    return a;
}
#define SWZ(x) ((x) ^ (((x) >> 3) & 0x70))

__device__ __forceinline__ void cpa16(uint32_t dst, const void* src) {
    asm volatile("cp.async.cg.shared.global [%0], [%1], 16;" :: "r"(dst), "l"(src) : "memory");
}

#define LDSM4(r, addr) \
    asm volatile("ldmatrix.sync.aligned.m8n8.x4.shared.b16 {%0,%1,%2,%3}, [%4];" \
        : "=r"((r)[0]), "=r"((r)[1]), "=r"((r)[2]), "=r"((r)[3]) : "r"(addr))

#define MMA16816(c, a, b) \
    asm volatile("mma.sync.aligned.m16n8k16.row.col.f32.f16.f16.f32 " \
        "{%0,%1,%2,%3}, {%4,%5,%6,%7}, {%8,%9}, {%0,%1,%2,%3};" \
        : "+f"((c)[0]), "+f"((c)[1]), "+f"((c)[2]), "+f"((c)[3]) \
        : "r"((a)[0]), "r"((a)[1]), "r"((a)[2]), "r"((a)[3]), \
          "r"((b)[0]), "r"((b)[1]))

// ---------------------------------------------------------------------------
// Kernel 1: gating (validated)
// ---------------------------------------------------------------------------
__global__ void gates_kernel(const float* __restrict__ x,
                             const float* __restrict__ Wg,
                             const float* __restrict__ bg) {
    int warp = (blockIdx.x * blockDim.x + threadIdx.x) >> 5;
    int lane = threadIdx.x & 31;
    if (warp >= B_) return;
    const float* xr = x + (size_t)warp * D_;
    float acc[E_];
#pragma unroll
    for (int e = 0; e < E_; e++) acc[e] = 0.f;
    for (int d = lane; d < D_; d += 32) {
        float xv = xr[d];
        const float4* w4 = reinterpret_cast<const float4*>(Wg + d * E_);
        float4 w0 = w4[0], w1 = w4[1];
        acc[0] += xv * w0.x; acc[1] += xv * w0.y;
        acc[2] += xv * w0.z; acc[3] += xv * w0.w;
        acc[4] += xv * w1.x; acc[5] += xv * w1.y;
        acc[6] += xv * w1.z; acc[7] += xv * w1.w;
    }
#pragma unroll
    for (int e = 0; e < E_; e++)
#pragma unroll
        for (int off = 16; off; off >>= 1)
            acc[e] += __shfl_xor_sync(0xffffffffu, acc[e], off);
    if (lane == 0) {
        float m = -1e30f;
#pragma unroll
        for (int e = 0; e < E_; e++) { acc[e] += bg[e]; m = fmaxf(m, acc[e]); }
        float s = 0.f;
#pragma unroll
        for (int e = 0; e < E_; e++) { acc[e] = expf(acc[e] - m); s += acc[e]; }
        float inv = 1.f / s;
#pragma unroll
        for (int e = 0; e < E_; e++) g_gates[warp * E_ + e] = acc[e] * inv;
    }
}

// ---------------------------------------------------------------------------
// Kernel 2: prescale — gx[e][b][d] = fp16(g[b][e] * x[b][d])
// ---------------------------------------------------------------------------
__global__ void prescale_kernel(const float* __restrict__ x) {
    size_t i = (size_t)blockIdx.x * 256 + threadIdx.x;   // over float4 groups
    int d4 = (int)(i & 255);
    int b  = (int)((i >> 8) & (B_ - 1));
    int e  = (int)(i >> 21);
    float g = g_gates[b * E_ + e];
    float4 v = reinterpret_cast<const float4*>(x)[(size_t)b * 256 + d4];
    __half h[4] = { __float2half_rn(g * v.x), __float2half_rn(g * v.y),
                    __float2half_rn(g * v.z), __float2half_rn(g * v.w) };
    size_t o = (((size_t)e * B_ + b) * D_ + d4 * 4);
    *reinterpret_cast<uint64_t*>(&g_gx[o]) = *reinterpret_cast<uint64_t*>(h);
}

// ---------------------------------------------------------------------------
// Kernel 3: transpose We[e][k][n] -> fp16 WeT[e][n][k]  (validated round 10)
// ---------------------------------------------------------------------------
__global__ void wt_kernel(const float* __restrict__ We) {
    __shared__ float t[32][33];
    int e = blockIdx.z;
    int k0 = blockIdx.y * 32, n0 = blockIdx.x * 32;
    int tx = threadIdx.x, ty = threadIdx.y;
    const float* base = We + ((size_t)e << 20);
#pragma unroll
    for (int j = 0; j < 4; j++)
        t[ty + j * 8][tx] = base[(size_t)(k0 + ty + j * 8) * O_ + n0 + tx];
    __syncthreads();
    size_t ob = ((size_t)e << 20);
#pragma unroll
    for (int j = 0; j < 4; j++)
        g_wt[ob + (size_t)(n0 + ty + j * 8) * D_ + k0 + tx] =
            __float2half_rn(t[tx][ty + j * 8]);
}

// ---------------------------------------------------------------------------
// Kernel 4: fused MoE GEMM — single fp16 product, K=8192 flat accumulation
//   out[b, n] = sum_{e,k} gx[e][b][k] * wt[e][n][k] + sum_e g[b][e]*be[e][n]
// ---------------------------------------------------------------------------
__global__ __launch_bounds__(256, 1)
void moe_fp16_kernel(const float* __restrict__ be, float* __restrict__ out) {
    extern __shared__ char smem[];
    const uint32_t sb = smem_u32(smem);
    const int tid = threadIdx.x;
    const int lane = tid & 31;
    const int wid = tid >> 5;
    const int warp_m = wid >> 1;        // 0..3  (64-row slabs)
    const int warp_n = wid & 1;         // 0..1  (64-col slabs)
    const int m0 = blockIdx.y * BM;
    const int n0 = blockIdx.x * BN;

    float* gs  = reinterpret_cast<float*>(smem + SM_GS);   // [8][256]
    float* bes = reinterpret_cast<float*>(smem + SM_BE);   // [8][128]
    for (int i = tid; i < E_ * BM; i += 256)
        gs[i] = g_gates[(size_t)(m0 + (i & 255)) * E_ + (i >> 8)];
    for (int i = tid; i < E_ * BN; i += 256)
        bes[i] = be[(i >> 7) * O_ + n0 + (i & 127)];

    float acc[4][8][4];
#pragma unroll
    for (int a = 0; a < 4; a++)
#pragma unroll
        for (int b = 0; b < 8; b++)
#pragma unroll
            for (int c = 0; c < 4; c++) acc[a][b][c] = 0.f;

    // stage loader: 12 x 16B cp.async per thread (A 32 KB + B 16 KB)
    auto issue = [&](int s) {
        const int e = s >> 4, kc = s & 15, koff = kc * KSTG;
        const uint32_t stg = sb + SM_ST + (s & 3) * STAGEB;
#pragma unroll
        for (int i = 0; i < 12; i++) {
            int c = tid + i * 256;
            if (c < 2048) {                 // A: 256 rows x 64 k
                int r = c >> 3, k16 = c & 7;
                uint32_t dst = stg + SWZ(r * 128 + k16 * 16);
                cpa16(dst, g_gx + (((size_t)e * B_ + m0 + r) * D_ + koff + k16 * 8));
            } else {                        // B: 128 rows x 64 k
                int cb = c - 2048;
                int r = cb >> 3, k16 = cb & 7;
                uint32_t dst = stg + A_BYTES + SWZ(r * 128 + k16 * 16);
                cpa16(dst, g_wt + (((size_t)e * O_ + n0 + r) * D_ + koff + k16 * 8));
            }
        }
        asm volatile("cp.async.commit_group;" ::: "memory");
    };

    issue(0); issue(1); issue(2);

    // ldmatrix lane address components
    const int a_row = lane & 15;
    const int a_kb  = lane >> 4;
    const int b_row = (lane & 7) + ((lane >> 4) << 3);
    const int b_kb  = (lane >> 3) & 1;

    for (int s = 0; s < NST; s++) {
        asm volatile("cp.async.wait_group 2;" ::: "memory");
        __syncthreads();
        if (s + 3 < NST) issue(s + 3);
        else asm volatile("cp.async.commit_group;" ::: "memory");

        const uint32_t stg = sb + SM_ST + (s & 3) * STAGEB;

#pragma unroll
        for (int kk = 0; kk < 4; kk++) {      // 4 k16 steps
            uint32_t a[4][4], bf[8][2];
#pragma unroll
            for (int mf = 0; mf < 4; mf++) {
                int row = warp_m * 64 + mf * 16 + a_row;
                LDSM4(a[mf], stg + SWZ(row * 128 + kk * 32 + a_kb * 16));
            }
#pragma unroll
            for (int nf2 = 0; nf2 < 4; nf2++) {
                int n = warp_n * 64 + nf2 * 16 + b_row;
                uint32_t t[4];
                LDSM4(t, stg + A_BYTES + SWZ(n * 128 + kk * 32 + b_kb * 16));
                bf[nf2 * 2][0] = t[0]; bf[nf2 * 2][1] = t[1];
                bf[nf2 * 2 + 1][0] = t[2]; bf[nf2 * 2 + 1][1] = t[3];
            }
#pragma unroll
            for (int mf = 0; mf < 4; mf++)
#pragma unroll
                for (int nf = 0; nf < 8; nf++)
                    MMA16816(acc[mf][nf], a[mf], bf[nf]);
        }
    }

    // epilogue: bias (sum_e g_e * be_e) + store
#pragma unroll
    for (int mf = 0; mf < 4; mf++) {
        int rl = warp_m * 64 + mf * 16 + (lane >> 2);
        float gl[E_], gh[E_];
#pragma unroll
        for (int e = 0; e < E_; e++) {
            gl[e] = gs[e * BM + rl];
            gh[e] = gs[e * BM + rl + 8];
        }
        size_t row_g = (size_t)(m0 + rl);
#pragma unroll
        for (int nf = 0; nf < 8; nf++) {
            int col = warp_n * 64 + nf * 8 + (lane & 3) * 2;
            float b00 = 0.f, b01 = 0.f, b10 = 0.f, b11 = 0.f;
#pragma unroll
            for (int e = 0; e < E_; e++) {
                float c0 = bes[e * BN + col], c1 = bes[e * BN + col + 1];
                b00 += gl[e] * c0; b01 += gl[e] * c1;
                b10 += gh[e] * c0; b11 += gh[e] * c1;
            }
            *reinterpret_cast<float2*>(out + row_g * O_ + n0 + col) =
                make_float2(acc[mf][nf][0] + b00, acc[mf][nf][1] + b01);
            *reinterpret_cast<float2*>(out + (row_g + 8) * O_ + n0 + col) =
                make_float2(acc[mf][nf][2] + b10, acc[mf][nf][3] + b11);
        }
    }
}

// ---------------------------------------------------------------------------
extern "C" void kernel_launch(void* const* d_in, const int* in_sizes, int n_in,
                              void* d_out, int out_size) {
    const float* x  = (const float*)d_in[0];   // [8192, 1024]
    const float* Wg = (const float*)d_in[1];   // [1024, 8]
    const float* bg = (const float*)d_in[2];   // [8]
    const float* We = (const float*)d_in[3];   // [8, 1024, 1024]
    const float* be = (const float*)d_in[4];   // [8, 1024]
    float* out = (float*)d_out;                // [8192, 1024]

    cudaFuncSetAttribute(moe_fp16_kernel,
                         cudaFuncAttributeMaxDynamicSharedMemorySize, SMEM_TOTAL);

    gates_kernel<<<B_ / 8, 256>>>(x, Wg, bg);
    prescale_kernel<<<(int)(((size_t)E_ * B_ * D_ / 4) / 256), 256>>>(x);
    wt_kernel<<<dim3(O_ / 32, D_ / 32, E_), dim3(32, 8)>>>(We);

    dim3 grid(O_ / BN, B_ / BM);               // (8, 32) = 256 CTAs
    moe_fp16_kernel<<<grid, 256, SMEM_TOTAL>>>(be, out);
}

// round 14
// speedup vs baseline: 7.3344x; 1.1314x over previous
#include <cuda_runtime.h>
#include <cuda_fp16.h>
#include <cstdint>

// ---------------------------------------------------------------------------
// Problem constants
// ---------------------------------------------------------------------------
#define B_  8192
#define D_  1024
#define O_  1024
#define E_  8

// GEMM tiling: CTA 128x128, 8 warps of 64x32, K=64 per stage, 2 CTAs/SM
#define BM 128
#define BN 128
#define KSTG 64
#define NST (E_ * D_ / KSTG)        // 128 stages (16 per expert)
#define A_BYTES (BM * 128)          // 16 KB
#define B_BYTES (BN * 128)          // 16 KB
#define STAGEB (A_BYTES + B_BYTES)  // 32 KB
#define NSTAGE 3

// SMEM layout
#define SM_GS 0                     // gates [8][128] f32 = 4 KB
#define SM_BE 4096                  // bias  [8][128] f32 = 4 KB
#define SM_ST 8192
#define SMEM_TOTAL (SM_ST + NSTAGE * STAGEB)   // 106496 (x2 CTAs fits 228KB)

// ---------------------------------------------------------------------------
// Scratch (device globals — no allocation)
// ---------------------------------------------------------------------------
__device__ float g_gates[B_ * E_];
__device__ __align__(16) __half g_gx[(size_t)E_ * B_ * D_];  // gate-scaled x, [e][b][d]
__device__ __align__(16) __half g_wt[E_ * O_ * D_];          // [e][n][k] K-major

// ---------------------------------------------------------------------------
// Helpers
// ---------------------------------------------------------------------------
__device__ __forceinline__ uint32_t smem_u32(const void* p) {
    uint32_t a;
    asm("{ .reg .u64 t; cvta.to.shared.u64 t, %1; cvt.u32.u64 %0, t; }" : "=r"(a) : "l"(p));
    return a;
}
#define SWZ(x) ((x) ^ (((x) >> 3) & 0x70))

__device__ __forceinline__ void cpa16(uint32_t dst, const void* src) {
    asm volatile("cp.async.cg.shared.global [%0], [%1], 16;" :: "r"(dst), "l"(src) : "memory");
}

#define LDSM4(r, addr) \
    asm volatile("ldmatrix.sync.aligned.m8n8.x4.shared.b16 {%0,%1,%2,%3}, [%4];" \
        : "=r"((r)[0]), "=r"((r)[1]), "=r"((r)[2]), "=r"((r)[3]) : "r"(addr))

#define MMA16816(c, a, b) \
    asm volatile("mma.sync.aligned.m16n8k16.row.col.f32.f16.f16.f32 " \
        "{%0,%1,%2,%3}, {%4,%5,%6,%7}, {%8,%9}, {%0,%1,%2,%3};" \
        : "+f"((c)[0]), "+f"((c)[1]), "+f"((c)[2]), "+f"((c)[3]) \
        : "r"((a)[0]), "r"((a)[1]), "r"((a)[2]), "r"((a)[3]), \
          "r"((b)[0]), "r"((b)[1]))

// ---------------------------------------------------------------------------
// Kernel 1: fused gating + prescale.
// One warp per row. Butterfly reduction leaves gate logits in ALL lanes, so
// every lane computes the softmax and participates in writing gx.
// ---------------------------------------------------------------------------
__global__ void gates_prescale_kernel(const float* __restrict__ x,
                                      const float* __restrict__ Wg,
                                      const float* __restrict__ bg) {
    int row = (blockIdx.x * blockDim.x + threadIdx.x) >> 5;
    int lane = threadIdx.x & 31;
    if (row >= B_) return;
    const float* xr = x + (size_t)row * D_;

    float acc[E_];
#pragma unroll
    for (int e = 0; e < E_; e++) acc[e] = 0.f;
    for (int d = lane; d < D_; d += 32) {
        float xv = xr[d];
        const float4* w4 = reinterpret_cast<const float4*>(Wg + d * E_);
        float4 w0 = w4[0], w1 = w4[1];
        acc[0] += xv * w0.x; acc[1] += xv * w0.y;
        acc[2] += xv * w0.z; acc[3] += xv * w0.w;
        acc[4] += xv * w1.x; acc[5] += xv * w1.y;
        acc[6] += xv * w1.z; acc[7] += xv * w1.w;
    }
#pragma unroll
    for (int e = 0; e < E_; e++)
#pragma unroll
        for (int off = 16; off; off >>= 1)
            acc[e] += __shfl_xor_sync(0xffffffffu, acc[e], off);

    // all lanes hold full sums -> all compute softmax
    float m = -1e30f;
#pragma unroll
    for (int e = 0; e < E_; e++) { acc[e] += bg[e]; m = fmaxf(m, acc[e]); }
    float s = 0.f;
#pragma unroll
    for (int e = 0; e < E_; e++) { acc[e] = expf(acc[e] - m); s += acc[e]; }
    float inv = 1.f / s;
#pragma unroll
    for (int e = 0; e < E_; e++) acc[e] *= inv;
    if (lane == 0) {
#pragma unroll
        for (int e = 0; e < E_; e++) g_gates[row * E_ + e] = acc[e];
    }

    // prescale: gx[e][row][d] = fp16(g_e * x[row][d]); x read once per warp
#pragma unroll
    for (int it = 0; it < 8; it++) {
        int idx = lane + it * 32;                       // float4 index 0..255
        float4 v = reinterpret_cast<const float4*>(xr)[idx];
#pragma unroll
        for (int e = 0; e < E_; e++) {
            float g = acc[e];
            __half h[4] = { __float2half_rn(g * v.x), __float2half_rn(g * v.y),
                            __float2half_rn(g * v.z), __float2half_rn(g * v.w) };
            size_t o = ((size_t)e * B_ + row) * D_ + idx * 4;
            *reinterpret_cast<uint64_t*>(&g_gx[o]) = *reinterpret_cast<uint64_t*>(h);
        }
    }
}

// ---------------------------------------------------------------------------
// Kernel 2: transpose We[e][k][n] -> fp16 WeT[e][n][k]  (validated)
// ---------------------------------------------------------------------------
__global__ void wt_kernel(const float* __restrict__ We) {
    __shared__ float t[32][33];
    int e = blockIdx.z;
    int k0 = blockIdx.y * 32, n0 = blockIdx.x * 32;
    int tx = threadIdx.x, ty = threadIdx.y;
    const float* base = We + ((size_t)e << 20);
#pragma unroll
    for (int j = 0; j < 4; j++)
        t[ty + j * 8][tx] = base[(size_t)(k0 + ty + j * 8) * O_ + n0 + tx];
    __syncthreads();
    size_t ob = ((size_t)e << 20);
#pragma unroll
    for (int j = 0; j < 4; j++)
        g_wt[ob + (size_t)(n0 + ty + j * 8) * D_ + k0 + tx] =
            __float2half_rn(t[tx][ty + j * 8]);
}

// ---------------------------------------------------------------------------
// Kernel 3: fused MoE GEMM — single fp16 product, K=8192 flat accumulation
//   out[b, n] = sum_{e,k} gx[e][b][k] * wt[e][n][k] + sum_e g[b][e]*be[e][n]
// ---------------------------------------------------------------------------
__global__ __launch_bounds__(256, 2)
void moe_fp16_kernel(const float* __restrict__ be, float* __restrict__ out) {
    extern __shared__ char smem[];
    const uint32_t sb = smem_u32(smem);
    const int tid = threadIdx.x;
    const int lane = tid & 31;
    const int wid = tid >> 5;
    const int warp_m = wid >> 2;        // 0..1  (64-row slabs)
    const int warp_n = wid & 3;         // 0..3  (32-col slabs)
    const int m0 = blockIdx.y * BM;
    const int n0 = blockIdx.x * BN;

    float* gs  = reinterpret_cast<float*>(smem + SM_GS);   // [8][128]
    float* bes = reinterpret_cast<float*>(smem + SM_BE);   // [8][128]
    for (int i = tid; i < E_ * BM; i += 256)
        gs[i] = g_gates[(size_t)(m0 + (i & 127)) * E_ + (i >> 7)];
    for (int i = tid; i < E_ * BN; i += 256)
        bes[i] = be[(i >> 7) * O_ + n0 + (i & 127)];

    float acc[4][4][4];
#pragma unroll
    for (int a = 0; a < 4; a++)
#pragma unroll
        for (int b = 0; b < 4; b++)
#pragma unroll
            for (int c = 0; c < 4; c++) acc[a][b][c] = 0.f;

    // stage loader: 8 x 16B cp.async per thread (A 16 KB + B 16 KB)
    auto issue = [&](int s) {
        const int e = s >> 4, kc = s & 15, koff = kc * KSTG;
        const uint32_t stg = sb + SM_ST + (s % NSTAGE) * STAGEB;
#pragma unroll
        for (int i = 0; i < 8; i++) {
            int c = tid + i * 256;
            if (c < 1024) {                 // A: 128 rows x 64 k
                int r = c >> 3, k16 = c & 7;
                uint32_t dst = stg + SWZ(r * 128 + k16 * 16);
                cpa16(dst, g_gx + (((size_t)e * B_ + m0 + r) * D_ + koff + k16 * 8));
            } else {                        // B: 128 rows x 64 k
                int cb = c - 1024;
                int r = cb >> 3, k16 = cb & 7;
                uint32_t dst = stg + A_BYTES + SWZ(r * 128 + k16 * 16);
                cpa16(dst, g_wt + (((size_t)e * O_ + n0 + r) * D_ + koff + k16 * 8));
            }
        }
        asm volatile("cp.async.commit_group;" ::: "memory");
    };

    issue(0); issue(1);

    // ldmatrix lane address components
    const int a_row = lane & 15;
    const int a_kb  = lane >> 4;
    const int b_row = (lane & 7) + ((lane >> 4) << 3);
    const int b_kb  = (lane >> 3) & 1;

    for (int s = 0; s < NST; s++) {
        asm volatile("cp.async.wait_group 1;" ::: "memory");
        __syncthreads();
        if (s + 2 < NST) issue(s + 2);

        const uint32_t stg = sb + SM_ST + (s % NSTAGE) * STAGEB;

#pragma unroll
        for (int kk = 0; kk < 4; kk++) {      // 4 k16 steps
            uint32_t a[4][4], bf[4][2];
#pragma unroll
            for (int mf = 0; mf < 4; mf++) {
                int row = warp_m * 64 + mf * 16 + a_row;
                LDSM4(a[mf], stg + SWZ(row * 128 + kk * 32 + a_kb * 16));
            }
#pragma unroll
            for (int nf2 = 0; nf2 < 2; nf2++) {
                int n = warp_n * 32 + nf2 * 16 + b_row;
                uint32_t t[4];
                LDSM4(t, stg + A_BYTES + SWZ(n * 128 + kk * 32 + b_kb * 16));
                bf[nf2 * 2][0] = t[0]; bf[nf2 * 2][1] = t[1];
                bf[nf2 * 2 + 1][0] = t[2]; bf[nf2 * 2 + 1][1] = t[3];
            }
#pragma unroll
            for (int mf = 0; mf < 4; mf++)
#pragma unroll
                for (int nf = 0; nf < 4; nf++)
                    MMA16816(acc[mf][nf], a[mf], bf[nf]);
        }
    }

    // epilogue: bias (sum_e g_e * be_e) + store
#pragma unroll
    for (int mf = 0; mf < 4; mf++) {
        int rl = warp_m * 64 + mf * 16 + (lane >> 2);
        size_t row_g = (size_t)(m0 + rl);
#pragma unroll
        for (int nf = 0; nf < 4; nf++) {
            int col = warp_n * 32 + nf * 8 + (lane & 3) * 2;
            float b00 = 0.f, b01 = 0.f, b10 = 0.f, b11 = 0.f;
#pragma unroll
            for (int e = 0; e < E_; e++) {
                float gl = gs[e * BM + rl], gh = gs[e * BM + rl + 8];
                float c0 = bes[e * BN + col], c1 = bes[e * BN + col + 1];
                b00 += gl * c0; b01 += gl * c1;
                b10 += gh * c0; b11 += gh * c1;
            }
            *reinterpret_cast<float2*>(out + row_g * O_ + n0 + col) =
                make_float2(acc[mf][nf][0] + b00, acc[mf][nf][1] + b01);
            *reinterpret_cast<float2*>(out + (row_g + 8) * O_ + n0 + col) =
                make_float2(acc[mf][nf][2] + b10, acc[mf][nf][3] + b11);
        }
    }
}

// ---------------------------------------------------------------------------
extern "C" void kernel_launch(void* const* d_in, const int* in_sizes, int n_in,
                              void* d_out, int out_size) {
    const float* x  = (const float*)d_in[0];   // [8192, 1024]
    const float* Wg = (const float*)d_in[1];   // [1024, 8]
    const float* bg = (const float*)d_in[2];   // [8]
    const float* We = (const float*)d_in[3];   // [8, 1024, 1024]
    const float* be = (const float*)d_in[4];   // [8, 1024]
    float* out = (float*)d_out;                // [8192, 1024]

    cudaFuncSetAttribute(moe_fp16_kernel,
                         cudaFuncAttributeMaxDynamicSharedMemorySize, SMEM_TOTAL);

    gates_prescale_kernel<<<B_ / 8, 256>>>(x, Wg, bg);
    wt_kernel<<<dim3(O_ / 32, D_ / 32, E_), dim3(32, 8)>>>(We);

    dim3 grid(O_ / BN, B_ / BM);               // (8, 64) = 512 CTAs
    moe_fp16_kernel<<<grid, 256, SMEM_TOTAL>>>(be, out);
}